// round 9
// baseline (speedup 1.0000x reference)
#include <cuda_runtime.h>

// LocSE fused kernel for GB300.
// Shapes (fixed): B=4, N=16384, DIMS=2, K1=17, UNITS=128, CH=53.
// Factorization: the (17 x 53) @ (53 x 64) per-neighborhood matmul
// = one shared 34-dim projection S[u] + a rank-3 per-j term.
// R9: 4-deep rotating prefetch on the feats gather (clamped indices, no guards),
// relu store issued before feats store; 7 CTAs/SM budget (<=36 regs).

#define NPTS   16384
#define BN     65536          // B*N
#define K1V    17
#define WARPS  8
#define OUT_FLOATS_PER_G 2176 // 17*128

__global__ __launch_bounds__(256, 7)
void locse_kernel(const float2* __restrict__ pc,      // (B,N) float2
                  const float2* __restrict__ feats,   // (B,N,32) float2 (64 floats)
                  const int*    __restrict__ nidx,    // (B,N,17)
                  const float*  __restrict__ W,       // (53,64)
                  const float*  __restrict__ bvec,    // (64,)
                  float2*       __restrict__ out,     // (B,N,17,64) float2
                  float2*       __restrict__ ggf)     // (B,N,1,2) as float2
{
    // sW4[i*32 + lane] = ( W[2+3i][2l], W[2+3i][2l+1], W[3+3i][2l], W[3+3i][2l+1] )
    __shared__ float4 sW4[K1V * 32];
    __shared__ float  sWx[64], sWy[64], sWn[64], sB[64];
    __shared__ float4 pts[WARPS][K1V];   // (x, y, norm, (ii*32)_as_float)

    const int tid = threadIdx.x;

    // ---- stage derived weights (once per block) ----
    if (tid < 64) {
        const int u = tid;
        float wx = W[u];          // W[0][u]
        float wy = W[64 + u];     // W[1][u]
        float wn = 0.f;
        #pragma unroll
        for (int i = 0; i < K1V; i++) {
            wx -= W[(2 + 3 * i) * 64 + u];
            wy -= W[(3 + 3 * i) * 64 + u];
            wn += W[(4 + 3 * i) * 64 + u];
        }
        sWx[u] = wx; sWy[u] = wy; sWn[u] = wn; sB[u] = bvec[u];
    }
    {
        float* sW4F = (float*)sW4;
        #pragma unroll 1
        for (int t = tid; t < K1V * 128; t += 256) {
            const int i = t >> 7;            // point index
            const int l = (t >> 2) & 31;     // lane
            const int c = t & 3;             // component
            const int row = (c < 2 ? 2 : 3) + 3 * i;
            const int col = 2 * l + (c & 1);
            sW4F[t] = W[row * 64 + col];
        }
    }
    __syncthreads();

    const int lane = tid & 31, warp = tid >> 5;
    const unsigned g = blockIdx.x * WARPS + warp;   // neighborhood id in [0, BN)
    const unsigned b = g >> 14;                     // g / 16384
    const int* __restrict__ ip = nidx + (size_t)g * K1V;

    // ---- phase A: gather 17 points, norms; stash feats offset (ii*32) ----
    float x = 0.f, y = 0.f;
    if (lane < K1V) {
        const int ii = ip[lane];
        const float2 p = pc[(size_t)b * NPTS + ii];
        x = p.x; y = p.y;
        const float nrm = sqrtf(x * x + y * y);
        pts[warp][lane] = make_float4(x, y, nrm, __int_as_float(ii * 32));
    }
    __syncwarp();

    // ---- ggf: two-pass centered stats over 17 points (matches reference) ----
    float sx = x, sy = y;
    #pragma unroll
    for (int o = 16; o; o >>= 1) {
        sx += __shfl_xor_sync(0xffffffffu, sx, o);
        sy += __shfl_xor_sync(0xffffffffu, sy, o);
    }
    const float inv17 = 1.0f / 17.0f;
    const float mx = sx * inv17, my = sy * inv17;
    const float xc = (lane < K1V) ? (x - mx) : 0.f;
    const float yc = (lane < K1V) ? (y - my) : 0.f;
    float sxx = xc * xc, syy = yc * yc, sxy = xc * yc;
    #pragma unroll
    for (int o = 16; o; o >>= 1) {
        sxx += __shfl_xor_sync(0xffffffffu, sxx, o);
        syy += __shfl_xor_sync(0xffffffffu, syy, o);
        sxy += __shfl_xor_sync(0xffffffffu, sxy, o);
    }
    if (lane == 0) {
        const float vx = sxx * inv17, vy = syy * inv17, cov = sxy * inv17;
        const float m    = cov / (vx + 1e-8f);
        const float pear = cov / (sqrtf(vx * vy) + 1e-8f);
        __stcs(ggf + g, make_float2(m, 1.0f - pear));
    }

    // ---- phase B: shared projection S[u]; one LDS.128 (pt) + one LDS.128 (w) per i ----
    float acc0 = sB[2 * lane], acc1 = sB[2 * lane + 1];
    #pragma unroll
    for (int i = 0; i < K1V; i++) {
        const float4 pt = pts[warp][i];                  // LDS broadcast
        const float4 w  = sW4[i * 32 + lane];
        acc0 = fmaf(pt.x, w.x, acc0);
        acc1 = fmaf(pt.x, w.y, acc1);
        acc0 = fmaf(pt.y, w.z, acc0);
        acc1 = fmaf(pt.y, w.w, acc1);
    }
    const float wx0 = sWx[2 * lane], wx1 = sWx[2 * lane + 1];
    const float wy0 = sWy[2 * lane], wy1 = sWy[2 * lane + 1];
    const float wn0 = sWn[2 * lane], wn1 = sWn[2 * lane + 1];

    // ---- phase C: 4-deep rotating prefetch on feats gather ----
    float2* __restrict__ outBase = out + (size_t)g * (OUT_FLOATS_PER_G / 2) + lane;
    const float2* __restrict__ fb = feats + (size_t)b * NPTS * 32 + lane;

    // gather offset for point j (scalar LDS broadcast of pts[j].w)
    #define WOF(j) __float_as_int(pts[warp][j].w)
    // compute + store row j; relu store first (independent of pending feats load)
    #define CST(j, fv) do {                                                   \
        const float4 pt = pts[warp][j];                                       \
        float r0 = fmaf(pt.z, wn0, fmaf(pt.y, wy0, fmaf(pt.x, wx0, acc0)));   \
        float r1 = fmaf(pt.z, wn1, fmaf(pt.y, wy1, fmaf(pt.x, wx1, acc1)));   \
        r0 = fmaxf(r0, 0.f); r1 = fmaxf(r1, 0.f);                             \
        float2* row = outBase + (j) * 64;                                     \
        __stcs(row + 32, make_float2(r0, r1));                                \
        __stcs(row, fv);                                                      \
    } while (0)

    float2 f0 = __ldcs(fb + WOF(0));
    float2 f1 = __ldcs(fb + WOF(1));
    float2 f2 = __ldcs(fb + WOF(2));
    float2 f3 = __ldcs(fb + WOF(3));

    #pragma unroll 1
    for (int j = 0; j < 16; j += 4) {
        CST(j + 0, f0);  f0 = __ldcs(fb + WOF(min(j + 4, 16)));
        CST(j + 1, f1);  f1 = __ldcs(fb + WOF(min(j + 5, 16)));
        CST(j + 2, f2);  f2 = __ldcs(fb + WOF(min(j + 6, 16)));
        CST(j + 3, f3);  f3 = __ldcs(fb + WOF(min(j + 7, 16)));
    }
    CST(16, f0);

    #undef WOF
    #undef CST
}

extern "C" void kernel_launch(void* const* d_in, const int* in_sizes, int n_in,
                              void* d_out, int out_size) {
    const float2* pc    = (const float2*)d_in[0];
    const float2* feats = (const float2*)d_in[1];
    const int*    nidx  = (const int*)d_in[2];
    const float*  W     = (const float*)d_in[3];
    const float*  bvec  = (const float*)d_in[4];

    float* out = (float*)d_out;
    // ggf tensor is concatenated after the main output
    float2* ggf = (float2*)(out + (size_t)BN * OUT_FLOATS_PER_G);

    locse_kernel<<<BN / WARPS, 256>>>(pc, feats, nidx, W, bvec,
                                      (float2*)out, ggf);
}

// round 10
// speedup vs baseline: 1.6200x; 1.6200x over previous
#include <cuda_runtime.h>

// LocSE fused kernel for GB300.
// Shapes (fixed): B=4, N=16384, DIMS=2, K1=17, UNITS=128, CH=53.
// Factorization: the (17 x 53) @ (53 x 64) per-neighborhood matmul
// = one shared 34-dim projection S[u] + a rank-3 per-j term.
// R10: group-of-4 gather MLP — per group: 4x LDS.128 (pts, read ONCE each),
// 4x LDG.64 back-to-back (default .ca caching), then 4x (FMA + 2x STG.64 .cs).
// launch_bounds(256,6); phase B uses float4-packed weights (1 LDS.128 each).

#define NPTS   16384
#define BN     65536          // B*N
#define K1V    17
#define WARPS  8
#define OUT_FLOATS_PER_G 2176 // 17*128

__global__ __launch_bounds__(256, 6)
void locse_kernel(const float2* __restrict__ pc,      // (B,N) float2
                  const float2* __restrict__ feats,   // (B,N,32) float2 (64 floats)
                  const int*    __restrict__ nidx,    // (B,N,17)
                  const float*  __restrict__ W,       // (53,64)
                  const float*  __restrict__ bvec,    // (64,)
                  float2*       __restrict__ out,     // (B,N,17,64) float2
                  float2*       __restrict__ ggf)     // (B,N,1,2) as float2
{
    // sW4[i*32 + lane] = ( W[2+3i][2l], W[2+3i][2l+1], W[3+3i][2l], W[3+3i][2l+1] )
    __shared__ float4 sW4[K1V * 32];
    __shared__ float  sWx[64], sWy[64], sWn[64], sB[64];
    __shared__ float4 pts[WARPS][K1V];   // (x, y, norm, (ii*32)_as_float)

    const int tid = threadIdx.x;

    // ---- stage derived weights (once per block) ----
    if (tid < 64) {
        const int u = tid;
        float wx = W[u];          // W[0][u]
        float wy = W[64 + u];     // W[1][u]
        float wn = 0.f;
        #pragma unroll
        for (int i = 0; i < K1V; i++) {
            wx -= W[(2 + 3 * i) * 64 + u];
            wy -= W[(3 + 3 * i) * 64 + u];
            wn += W[(4 + 3 * i) * 64 + u];
        }
        sWx[u] = wx; sWy[u] = wy; sWn[u] = wn; sB[u] = bvec[u];
    }
    {
        float* sW4F = (float*)sW4;
        #pragma unroll 1
        for (int t = tid; t < K1V * 128; t += 256) {
            const int i = t >> 7;            // point index
            const int l = (t >> 2) & 31;     // lane
            const int c = t & 3;             // component
            const int row = (c < 2 ? 2 : 3) + 3 * i;
            const int col = 2 * l + (c & 1);
            sW4F[t] = W[row * 64 + col];
        }
    }
    __syncthreads();

    const int lane = tid & 31, warp = tid >> 5;
    const unsigned g = blockIdx.x * WARPS + warp;   // neighborhood id in [0, BN)
    const unsigned b = g >> 14;                     // g / 16384
    const int* __restrict__ ip = nidx + (size_t)g * K1V;

    // ---- phase A: gather 17 points, norms; stash feats offset (ii*32) ----
    float x = 0.f, y = 0.f;
    if (lane < K1V) {
        const int ii = ip[lane];
        const float2 p = pc[(size_t)b * NPTS + ii];
        x = p.x; y = p.y;
        const float nrm = sqrtf(x * x + y * y);
        pts[warp][lane] = make_float4(x, y, nrm, __int_as_float(ii * 32));
    }
    __syncwarp();

    // ---- ggf: two-pass centered stats over 17 points (matches reference) ----
    float sx = x, sy = y;
    #pragma unroll
    for (int o = 16; o; o >>= 1) {
        sx += __shfl_xor_sync(0xffffffffu, sx, o);
        sy += __shfl_xor_sync(0xffffffffu, sy, o);
    }
    const float inv17 = 1.0f / 17.0f;
    const float mx = sx * inv17, my = sy * inv17;
    const float xc = (lane < K1V) ? (x - mx) : 0.f;
    const float yc = (lane < K1V) ? (y - my) : 0.f;
    float sxx = xc * xc, syy = yc * yc, sxy = xc * yc;
    #pragma unroll
    for (int o = 16; o; o >>= 1) {
        sxx += __shfl_xor_sync(0xffffffffu, sxx, o);
        syy += __shfl_xor_sync(0xffffffffu, syy, o);
        sxy += __shfl_xor_sync(0xffffffffu, sxy, o);
    }
    if (lane == 0) {
        const float vx = sxx * inv17, vy = syy * inv17, cov = sxy * inv17;
        const float m    = cov / (vx + 1e-8f);
        const float pear = cov / (sqrtf(vx * vy) + 1e-8f);
        __stcs(ggf + g, make_float2(m, 1.0f - pear));
    }

    // ---- phase B: shared projection S[u]; one LDS.128 (pt) + one LDS.128 (w) per i ----
    float acc0 = sB[2 * lane], acc1 = sB[2 * lane + 1];
    #pragma unroll
    for (int i = 0; i < K1V; i++) {
        const float4 pt = pts[warp][i];                  // LDS broadcast
        const float4 w  = sW4[i * 32 + lane];
        acc0 = fmaf(pt.x, w.x, acc0);
        acc1 = fmaf(pt.x, w.y, acc1);
        acc0 = fmaf(pt.y, w.z, acc0);
        acc1 = fmaf(pt.y, w.w, acc1);
    }
    const float wx0 = sWx[2 * lane], wx1 = sWx[2 * lane + 1];
    const float wy0 = sWy[2 * lane], wy1 = sWy[2 * lane + 1];
    const float wn0 = sWn[2 * lane], wn1 = sWn[2 * lane + 1];

    // ---- phase C: group-of-4 gather MLP; pts read exactly once per j ----
    float2* __restrict__ outBase = out + (size_t)g * (OUT_FLOATS_PER_G / 2) + lane;
    const float2* __restrict__ fb = feats + (size_t)b * NPTS * 32 + lane;

    #define CST(j, pt, fv) do {                                               \
        float r0 = fmaf((pt).z, wn0, fmaf((pt).y, wy0, fmaf((pt).x, wx0, acc0))); \
        float r1 = fmaf((pt).z, wn1, fmaf((pt).y, wy1, fmaf((pt).x, wx1, acc1))); \
        r0 = fmaxf(r0, 0.f); r1 = fmaxf(r1, 0.f);                             \
        float2* row = outBase + (j) * 64;                                     \
        __stcs(row, fv);                                                      \
        __stcs(row + 32, make_float2(r0, r1));                                \
    } while (0)

    #pragma unroll 1
    for (int j = 0; j < 16; j += 4) {
        // read the 4 pts ONCE into registers
        const float4 p0 = pts[warp][j];
        const float4 p1 = pts[warp][j + 1];
        const float4 p2 = pts[warp][j + 2];
        const float4 p3 = pts[warp][j + 3];
        // 4 independent gathers in flight (default .ca caching for L1 reuse)
        const float2 q0 = fb[__float_as_int(p0.w)];
        const float2 q1 = fb[__float_as_int(p1.w)];
        const float2 q2 = fb[__float_as_int(p2.w)];
        const float2 q3 = fb[__float_as_int(p3.w)];
        CST(j + 0, p0, q0);
        CST(j + 1, p1, q1);
        CST(j + 2, p2, q2);
        CST(j + 3, p3, q3);
    }
    {
        const float4 p = pts[warp][16];
        const float2 q = fb[__float_as_int(p.w)];
        CST(16, p, q);
    }
    #undef CST
}

extern "C" void kernel_launch(void* const* d_in, const int* in_sizes, int n_in,
                              void* d_out, int out_size) {
    const float2* pc    = (const float2*)d_in[0];
    const float2* feats = (const float2*)d_in[1];
    const int*    nidx  = (const int*)d_in[2];
    const float*  W     = (const float*)d_in[3];
    const float*  bvec  = (const float*)d_in[4];

    float* out = (float*)d_out;
    // ggf tensor is concatenated after the main output
    float2* ggf = (float2*)(out + (size_t)BN * OUT_FLOATS_PER_G);

    locse_kernel<<<BN / WARPS, 256>>>(pc, feats, nidx, W, bvec,
                                      (float2*)out, ggf);
}

// round 11
// speedup vs baseline: 1.6501x; 1.0186x over previous
#include <cuda_runtime.h>

// LocSE fused kernel for GB300.
// Shapes (fixed): B=4, N=16384, DIMS=2, K1=17, UNITS=128, CH=53.
// Factorization: the (17 x 53) @ (53 x 64) per-neighborhood matmul
// = one shared 34-dim projection S[u] + a rank-3 per-j term.
// R11: R10 body (group-of-4 gather MLP, pts read once per j) at 7 CTAs/SM
// (launch_bounds(256,7)) -> 56 warps x MLP4 in flight per SM.

#define NPTS   16384
#define BN     65536          // B*N
#define K1V    17
#define WARPS  8
#define OUT_FLOATS_PER_G 2176 // 17*128

__global__ __launch_bounds__(256, 7)
void locse_kernel(const float2* __restrict__ pc,      // (B,N) float2
                  const float2* __restrict__ feats,   // (B,N,32) float2 (64 floats)
                  const int*    __restrict__ nidx,    // (B,N,17)
                  const float*  __restrict__ W,       // (53,64)
                  const float*  __restrict__ bvec,    // (64,)
                  float2*       __restrict__ out,     // (B,N,17,64) float2
                  float2*       __restrict__ ggf)     // (B,N,1,2) as float2
{
    // sW4[i*32 + lane] = ( W[2+3i][2l], W[2+3i][2l+1], W[3+3i][2l], W[3+3i][2l+1] )
    __shared__ float4 sW4[K1V * 32];
    __shared__ float  sWx[64], sWy[64], sWn[64], sB[64];
    __shared__ float4 pts[WARPS][K1V];   // (x, y, norm, (ii*32)_as_float)

    const int tid = threadIdx.x;

    // ---- stage derived weights (once per block) ----
    if (tid < 64) {
        const int u = tid;
        float wx = W[u];          // W[0][u]
        float wy = W[64 + u];     // W[1][u]
        float wn = 0.f;
        #pragma unroll
        for (int i = 0; i < K1V; i++) {
            wx -= W[(2 + 3 * i) * 64 + u];
            wy -= W[(3 + 3 * i) * 64 + u];
            wn += W[(4 + 3 * i) * 64 + u];
        }
        sWx[u] = wx; sWy[u] = wy; sWn[u] = wn; sB[u] = bvec[u];
    }
    {
        float* sW4F = (float*)sW4;
        #pragma unroll 1
        for (int t = tid; t < K1V * 128; t += 256) {
            const int i = t >> 7;            // point index
            const int l = (t >> 2) & 31;     // lane
            const int c = t & 3;             // component
            const int row = (c < 2 ? 2 : 3) + 3 * i;
            const int col = 2 * l + (c & 1);
            sW4F[t] = W[row * 64 + col];
        }
    }
    __syncthreads();

    const int lane = tid & 31, warp = tid >> 5;
    const unsigned g = blockIdx.x * WARPS + warp;   // neighborhood id in [0, BN)
    const unsigned b = g >> 14;                     // g / 16384
    const int* __restrict__ ip = nidx + (size_t)g * K1V;

    // ---- phase A: gather 17 points, norms; stash feats offset (ii*32) ----
    float x = 0.f, y = 0.f;
    if (lane < K1V) {
        const int ii = ip[lane];
        const float2 p = pc[(size_t)b * NPTS + ii];
        x = p.x; y = p.y;
        const float nrm = sqrtf(x * x + y * y);
        pts[warp][lane] = make_float4(x, y, nrm, __int_as_float(ii * 32));
    }
    __syncwarp();

    // ---- ggf: two-pass centered stats over 17 points (matches reference) ----
    float sx = x, sy = y;
    #pragma unroll
    for (int o = 16; o; o >>= 1) {
        sx += __shfl_xor_sync(0xffffffffu, sx, o);
        sy += __shfl_xor_sync(0xffffffffu, sy, o);
    }
    const float inv17 = 1.0f / 17.0f;
    const float mx = sx * inv17, my = sy * inv17;
    const float xc = (lane < K1V) ? (x - mx) : 0.f;
    const float yc = (lane < K1V) ? (y - my) : 0.f;
    float sxx = xc * xc, syy = yc * yc, sxy = xc * yc;
    #pragma unroll
    for (int o = 16; o; o >>= 1) {
        sxx += __shfl_xor_sync(0xffffffffu, sxx, o);
        syy += __shfl_xor_sync(0xffffffffu, syy, o);
        sxy += __shfl_xor_sync(0xffffffffu, sxy, o);
    }
    if (lane == 0) {
        const float vx = sxx * inv17, vy = syy * inv17, cov = sxy * inv17;
        const float m    = cov / (vx + 1e-8f);
        const float pear = cov / (sqrtf(vx * vy) + 1e-8f);
        __stcs(ggf + g, make_float2(m, 1.0f - pear));
    }

    // ---- phase B: shared projection S[u]; one LDS.128 (pt) + one LDS.128 (w) per i ----
    float acc0 = sB[2 * lane], acc1 = sB[2 * lane + 1];
    #pragma unroll
    for (int i = 0; i < K1V; i++) {
        const float4 pt = pts[warp][i];                  // LDS broadcast
        const float4 w  = sW4[i * 32 + lane];
        acc0 = fmaf(pt.x, w.x, acc0);
        acc1 = fmaf(pt.x, w.y, acc1);
        acc0 = fmaf(pt.y, w.z, acc0);
        acc1 = fmaf(pt.y, w.w, acc1);
    }
    const float wx0 = sWx[2 * lane], wx1 = sWx[2 * lane + 1];
    const float wy0 = sWy[2 * lane], wy1 = sWy[2 * lane + 1];
    const float wn0 = sWn[2 * lane], wn1 = sWn[2 * lane + 1];

    // ---- phase C: group-of-4 gather MLP; pts read exactly once per j ----
    float2* __restrict__ outBase = out + (size_t)g * (OUT_FLOATS_PER_G / 2) + lane;
    const float2* __restrict__ fb = feats + (size_t)b * NPTS * 32 + lane;

    #define CST(j, pt, fv) do {                                               \
        float r0 = fmaf((pt).z, wn0, fmaf((pt).y, wy0, fmaf((pt).x, wx0, acc0))); \
        float r1 = fmaf((pt).z, wn1, fmaf((pt).y, wy1, fmaf((pt).x, wx1, acc1))); \
        r0 = fmaxf(r0, 0.f); r1 = fmaxf(r1, 0.f);                             \
        float2* row = outBase + (j) * 64;                                     \
        __stcs(row, fv);                                                      \
        __stcs(row + 32, make_float2(r0, r1));                                \
    } while (0)

    #pragma unroll 1
    for (int j = 0; j < 16; j += 4) {
        // read the 4 pts ONCE into registers
        const float4 p0 = pts[warp][j];
        const float4 p1 = pts[warp][j + 1];
        const float4 p2 = pts[warp][j + 2];
        const float4 p3 = pts[warp][j + 3];
        // 4 independent gathers in flight
        const float2 q0 = fb[__float_as_int(p0.w)];
        const float2 q1 = fb[__float_as_int(p1.w)];
        const float2 q2 = fb[__float_as_int(p2.w)];
        const float2 q3 = fb[__float_as_int(p3.w)];
        CST(j + 0, p0, q0);
        CST(j + 1, p1, q1);
        CST(j + 2, p2, q2);
        CST(j + 3, p3, q3);
    }
    {
        const float4 p = pts[warp][16];
        const float2 q = fb[__float_as_int(p.w)];
        CST(16, p, q);
    }
    #undef CST
}

extern "C" void kernel_launch(void* const* d_in, const int* in_sizes, int n_in,
                              void* d_out, int out_size) {
    const float2* pc    = (const float2*)d_in[0];
    const float2* feats = (const float2*)d_in[1];
    const int*    nidx  = (const int*)d_in[2];
    const float*  W     = (const float*)d_in[3];
    const float*  bvec  = (const float*)d_in[4];

    float* out = (float*)d_out;
    // ggf tensor is concatenated after the main output
    float2* ggf = (float2*)(out + (size_t)BN * OUT_FLOATS_PER_G);

    locse_kernel<<<BN / WARPS, 256>>>(pc, feats, nidx, W, bvec,
                                      (float2*)out, ggf);
}